// round 11
// baseline (speedup 1.0000x reference)
#include <cuda_runtime.h>
#include <cstdint>

// ---------------------------------------------------------------------------
// TripletLoss, single kernel, fully block-local dataflow (no grid barrier).
//   B=384, D=256, C=48. JAX-exact gumbel via threefry2x32 (partitionable,
//   bits = x0^x1, key=[0,42]) evaluated only at semi-hard sites.
//   96 blocks x 384 threads; block owns 4 anchors (96*4 = 384).
//   Phase A: anchors negated in registers; warp-per-point distance
//            (coalesced LDG.128, f32x2 packed math, xor-shfl reduce)
//            -> s_dist[4][B] in SHARED memory. No global dist matrix.
//   Phase B: block-local pair enumeration + warp-per-pair gumbel argmax
//            reading dist from smem; gumbel inlined so iterations overlap.
//   Finalize: per-block atomicAdd; last-done block writes scalar + resets.
// ---------------------------------------------------------------------------

#define B 384
#define D 256
#define MARGIN 0.2f
#define TINYF 1.17549435e-38f
#define NBLK 96
#define NTHR 384
#define APB 4                         // anchors per block
#define DPITCH (B + 4)                // 388 floats: stride%32==4, conflict-free
#define PLMAX 1536

typedef unsigned long long u64;

// packed f32x2 helpers (Blackwell sm_103a)
#define ADD2(out, a, b) \
    asm("add.rn.f32x2 %0, %1, %2;" : "=l"(out) : "l"(a), "l"(b))
#define FMA2(acc, d) \
    asm("fma.rn.f32x2 %0, %1, %1, %0;" : "+l"(acc) : "l"(d))

// ---- persistent device state (reset by finalizer each run) -----------------
__device__ float    g_total = 0.0f;
__device__ int      g_count = 0;
__device__ unsigned g_done  = 0;

// ---- threefry2x32, JAX schedule, key = [0, 42] ------------------------------
__device__ __forceinline__ uint32_t rotl32(uint32_t x, int d) {
    return __funnelshift_l(x, x, d);
}

__device__ __forceinline__ float gumbel_at(uint32_t n) {
    // counter = (0, n) since n < 384^3 < 2^32 ; key = [0, 42]
    const uint32_t k0 = 0u, k1 = 42u;
    const uint32_t k2 = k0 ^ k1 ^ 0x1BD11BDAu;
    uint32_t x0 = 0u + k0, x1 = n + k1;
#define TF_RND(r) { x0 += x1; x1 = rotl32(x1, (r)); x1 ^= x0; }
    TF_RND(13) TF_RND(15) TF_RND(26) TF_RND(6)
    x0 += k1; x1 += k2 + 1u;
    TF_RND(17) TF_RND(29) TF_RND(16) TF_RND(24)
    x0 += k2; x1 += k0 + 2u;
    TF_RND(13) TF_RND(15) TF_RND(26) TF_RND(6)
    x0 += k0; x1 += k1 + 3u;
    TF_RND(17) TF_RND(29) TF_RND(16) TF_RND(24)
    x0 += k1; x1 += k2 + 4u;
    TF_RND(13) TF_RND(15) TF_RND(26) TF_RND(6)
    x0 += k2; x1 += k0 + 5u;
#undef TF_RND
    uint32_t bits = x0 ^ x1;   // partitionable 32-bit draw
    float f = __uint_as_float((bits >> 9) | 0x3f800000u) - 1.0f;
    float u = fmaxf(TINYF, f + TINYF);
    return -logf(-logf(u));
}

// negate+pack two floats into a f32x2 u64
__device__ __forceinline__ u64 packneg(float a, float b) {
    float2 t; t.x = -a; t.y = -b;
    return *(u64*)&t;
}
__device__ __forceinline__ u64 pack2(float a, float b) {
    float2 t; t.x = a; t.y = b;
    return *(u64*)&t;
}

// ---- the kernel --------------------------------------------------------------
__global__ void __launch_bounds__(NTHR)
k_fused(const float* __restrict__ f, const int* __restrict__ labels,
        const int* __restrict__ epoch, float* __restrict__ out) {
    __shared__ float s_dist[APB][DPITCH];
    __shared__ int   s_lab[B];
    __shared__ int   s_plist[PLMAX];
    __shared__ int   s_np;
    __shared__ float s_total;
    __shared__ int   s_count;

    const int tid  = threadIdx.x;
    const int bid  = blockIdx.x;
    const int lane = tid & 31;
    const int w    = tid >> 5;
    const int i0   = bid * APB;

    s_lab[tid] = labels[tid];
    if (tid == 0) { s_np = 0; s_total = 0.0f; s_count = 0; }

    // ---- anchor rows, negated, in registers (lane: dims 4l..4l+3, 128+4l..) --
    u64 nA[APB][4];
#pragma unroll
    for (int a = 0; a < APB; a++) {
        float4 xa = *(const float4*)&f[(i0 + a) * D + lane * 4];
        float4 xb = *(const float4*)&f[(i0 + a) * D + 128 + lane * 4];
        nA[a][0] = packneg(xa.x, xa.y);
        nA[a][1] = packneg(xa.z, xa.w);
        nA[a][2] = packneg(xb.x, xb.y);
        nA[a][3] = packneg(xb.z, xb.w);
    }
    __syncthreads();     // labels visible to enumeration warps

    // ---- phase A: warp-per-point distances -> s_dist -------------------------
    for (int it = 0; it < 32; it += 2) {
        const int k0 = w * 32 + it;
        const int k1 = k0 + 1;
        float4 p0a = *(const float4*)&f[k0 * D + lane * 4];
        float4 p0b = *(const float4*)&f[k0 * D + 128 + lane * 4];
        float4 p1a = *(const float4*)&f[k1 * D + lane * 4];
        float4 p1b = *(const float4*)&f[k1 * D + 128 + lane * 4];
        u64 q0[4] = { pack2(p0a.x, p0a.y), pack2(p0a.z, p0a.w),
                      pack2(p0b.x, p0b.y), pack2(p0b.z, p0b.w) };
        u64 q1[4] = { pack2(p1a.x, p1a.y), pack2(p1a.z, p1a.w),
                      pack2(p1b.x, p1b.y), pack2(p1b.z, p1b.w) };

        float v0[APB], v1[APB];
#pragma unroll
        for (int a = 0; a < APB; a++) {
            u64 acc0 = 0, acc1 = 0, d;
#pragma unroll
            for (int h = 0; h < 4; h++) {
                ADD2(d, q0[h], nA[a][h]); FMA2(acc0, d);
                ADD2(d, q1[h], nA[a][h]); FMA2(acc1, d);
            }
            float2 t0 = *(float2*)&acc0, t1 = *(float2*)&acc1;
            v0[a] = t0.x + t0.y;
            v1[a] = t1.x + t1.y;
        }
        // xor-butterfly reductions (all lanes end with the sum)
#pragma unroll
        for (int a = 0; a < APB; a++) {
#pragma unroll
            for (int off = 16; off; off >>= 1) {
                v0[a] += __shfl_xor_sync(0xffffffffu, v0[a], off);
                v1[a] += __shfl_xor_sync(0xffffffffu, v1[a], off);
            }
        }
        // lane a (<4) stores anchor a's distance for both points
        float s0 = v0[0], s1 = v1[0];
        s0 = (lane == 1) ? v0[1] : s0;  s1 = (lane == 1) ? v1[1] : s1;
        s0 = (lane == 2) ? v0[2] : s0;  s1 = (lane == 2) ? v1[2] : s1;
        s0 = (lane == 3) ? v0[3] : s0;  s1 = (lane == 3) ? v1[3] : s1;
        if (lane < APB) {
            s_dist[lane][k0] = sqrtf(fmaxf(s0, 1e-11f));
            s_dist[lane][k1] = sqrtf(fmaxf(s1, 1e-11f));
        }
    }

    // ---- pair enumeration: warp a scans anchor i0+a --------------------------
    if (w < APB) {
        const int i = i0 + w;
        const int li = s_lab[i];
#pragma unroll
        for (int s = 0; s < B / 32; s++) {
            const int p = s * 32 + lane;
            const bool valid = (p > i) && (s_lab[p] == li);
            const unsigned m = __ballot_sync(0xffffffffu, valid);
            if (m) {
                int base = 0;
                if (lane == 0) base = atomicAdd(&s_np, __popc(m));
                base = __shfl_sync(0xffffffffu, base, 0);
                if (valid) {
                    int slot = base + __popc(m & ((1u << lane) - 1u));
                    if (slot < PLMAX) s_plist[slot] = (w << 16) | p;
                }
            }
        }
    }
    __syncthreads();     // s_dist + s_plist complete

    // ---- phase B: one warp per pair, dist from smem ---------------------------
    const bool semi_mode = (epoch[0] > 3);
    const int np = s_np;
    float wsum = 0.0f;
    int   wcnt = 0;

    for (int q = w; q < np; q += NTHR / 32) {
        const int code = s_plist[q];
        const int a = code >> 16, p = code & 0xffff;
        const int i = i0 + a;
        const int li = s_lab[i];
        const float* drow = s_dist[a];
        const float dpos = drow[p];
        const uint32_t nbase = ((uint32_t)i * B + p) * B;

        float best = -3.0e38f;
        int   bidx = 0x7fffffff;
        bool  anyf = false;
#pragma unroll 2
        for (int s = 0; s < B / 32; s++) {
            const int k = s * 32 + lane;
            const float dik = drow[k];                 // conflict-free LDS
            const bool neg = (s_lab[k] != li);
            const bool semi = semi_mode
                ? (neg && dik > dpos && dik < dpos + MARGIN) : neg;
            if (semi) {
                anyf = true;
                float base = semi_mode ? -logf(dik) : 0.0f;
                float sc = base + gumbel_at(nbase + k);
                if (sc > best || (sc == best && k < bidx)) { best = sc; bidx = k; }
            }
        }
        // warp argmax, first-index tie break (matches jnp.argmax)
#pragma unroll
        for (int off = 16; off; off >>= 1) {
            float ov = __shfl_down_sync(0xffffffffu, best, off);
            int   oi = __shfl_down_sync(0xffffffffu, bidx, off);
            if (ov > best || (ov == best && oi < bidx)) { best = ov; bidx = oi; }
        }
        const bool any = __any_sync(0xffffffffu, anyf);
        if (lane == 0 && any) {
            wsum += fmaxf(dpos - drow[bidx] + MARGIN, 0.0f);
            wcnt += 1;
        }
    }

    if (lane == 0 && wcnt > 0) {
        atomicAdd(&s_total, wsum);
        atomicAdd(&s_count, wcnt);
    }
    __syncthreads();
    if (tid == 0 && s_count > 0) {
        atomicAdd(&g_total, s_total);
        atomicAdd(&g_count, s_count);
    }

    // ---- finalize: last block writes the result & resets persistent state ----
    __threadfence();
    if (tid == 0) {
        if (atomicAdd(&g_done, 1u) == gridDim.x - 1) {
            float tot = atomicAdd(&g_total, 0.0f);   // atomic read-after-fence
            int   cnt = atomicAdd(&g_count, 0);
            out[0] = (cnt > 0) ? (tot / (float)cnt) : 0.0f;
            g_total = 0.0f;
            g_count = 0;
            __threadfence();
            atomicExch(&g_done, 0u);
        }
    }
}

// ---- launch ------------------------------------------------------------------
extern "C" void kernel_launch(void* const* d_in, const int* in_sizes, int n_in,
                              void* d_out, int out_size) {
    const float* feat   = (const float*)d_in[0];
    const int*   labels = (const int*)d_in[1];
    const int*   epoch  = (const int*)d_in[2];
    float* out = (float*)d_out;

    k_fused<<<NBLK, NTHR>>>(feat, labels, epoch, out);
}

// round 12
// speedup vs baseline: 1.7900x; 1.7900x over previous
#include <cuda_runtime.h>
#include <cstdint>

// ---------------------------------------------------------------------------
// TripletLoss, single fused persistent kernel. R8 skeleton; phase B rewritten:
// batched candidate loads (MLP=12) + fully-inlined gumbel so the threefry/logf
// chains overlap across lanes instead of serializing behind a call boundary.
//   B=384, D=256, C=48. JAX-exact gumbel via threefry2x32 (partitionable,
//   bits = x0^x1, key=[0,42]) evaluated only at semi-hard sites.
// ---------------------------------------------------------------------------

#define B 384
#define D 256
#define MARGIN 0.2f
#define TINYF 1.17549435e-38f
#define NBLK 144
#define NTHR 512
#define TILE 32
#define PITCH 36                      // floats; 144B rows, 16B-aligned float4
#define NPAIR_MAX ((B * (B - 1)) / 2)

typedef unsigned long long u64;

// packed f32x2 helpers (Blackwell sm_103a; ptxas never emits these from C++)
#define ADD2(out, a, b) \
    asm("add.rn.f32x2 %0, %1, %2;" : "=l"(out) : "l"(a), "l"(b))
#define FMA2(acc, d) \
    asm("fma.rn.f32x2 %0, %1, %1, %0;" : "+l"(acc) : "l"(d))

// ---- persistent device state (restored to initial values every run) -------
__device__ float    g_dist[B * B];
__device__ int      g_pairlist[NPAIR_MAX];
__device__ int      g_npairs = 0;
__device__ float    g_total  = 0.0f;
__device__ int      g_count  = 0;
__device__ unsigned g_done   = 0;
__device__ unsigned g_barcnt = 0;
__device__ volatile unsigned g_sense = 0;

// ---- threefry2x32, JAX schedule, key = [0, 42] -----------------------------
__device__ __forceinline__ uint32_t rotl32(uint32_t x, int d) {
    return __funnelshift_l(x, x, d);
}

__device__ __forceinline__ float gumbel_at(uint32_t n) {
    // counter = (0, n) since n < 384^3 < 2^32 ; key = [0, 42]
    const uint32_t k0 = 0u, k1 = 42u;
    const uint32_t k2 = k0 ^ k1 ^ 0x1BD11BDAu;
    uint32_t x0 = 0u + k0, x1 = n + k1;
#define TF_RND(r) { x0 += x1; x1 = rotl32(x1, (r)); x1 ^= x0; }
    TF_RND(13) TF_RND(15) TF_RND(26) TF_RND(6)
    x0 += k1; x1 += k2 + 1u;
    TF_RND(17) TF_RND(29) TF_RND(16) TF_RND(24)
    x0 += k2; x1 += k0 + 2u;
    TF_RND(13) TF_RND(15) TF_RND(26) TF_RND(6)
    x0 += k0; x1 += k1 + 3u;
    TF_RND(17) TF_RND(29) TF_RND(16) TF_RND(24)
    x0 += k1; x1 += k2 + 4u;
    TF_RND(13) TF_RND(15) TF_RND(26) TF_RND(6)
    x0 += k2; x1 += k0 + 5u;
#undef TF_RND
    uint32_t bits = x0 ^ x1;   // partitionable 32-bit draw
    float f = __uint_as_float((bits >> 9) | 0x3f800000u) - 1.0f;
    float u = fmaxf(TINYF, f + TINYF);
    return -logf(-logf(u));
}

// ---- sense-reversing grid barrier (144 blocks <= 148 SMs, 1/SM resident) ---
__device__ __forceinline__ void grid_barrier() {
    __syncthreads();
    __threadfence();
    if (threadIdx.x == 0) {
        unsigned s = g_sense;
        if (atomicAdd(&g_barcnt, 1u) == gridDim.x - 1) {
            atomicExch(&g_barcnt, 0u);
            __threadfence();
            g_sense = s ^ 1u;
        } else {
            while (g_sense == s) { }
        }
    }
    __syncthreads();
}

// ---- the fused kernel --------------------------------------------------------
__global__ void __launch_bounds__(NTHR)
k_fused(const float* __restrict__ f, const int* __restrict__ labels,
        const int* __restrict__ epoch, float* __restrict__ out) {
    __shared__ __align__(16) float As[2][TILE][PITCH];
    __shared__ __align__(16) float Bs[2][TILE][PITCH];   // holds NEGATED rows
    __shared__ int   s_lab[B];
    __shared__ int   s_pbuf[128];
    __shared__ int   s_pcnt;
    __shared__ float s_total;
    __shared__ int   s_count;

    const int tid = threadIdx.x;
    const int bid = blockIdx.x;

    if (tid < B) s_lab[tid] = labels[tid];
    if (tid == 0) { s_total = 0.0f; s_count = 0; s_pcnt = 0; }
    __syncthreads();

    // ---- phase A1: pair compaction, smem-local then one global atomic ------
#pragma unroll
    for (int e = 0; e < 2; e++) {
        int idx = bid * 1024 + e * NTHR + tid;
        int i = idx / B, p = idx - i * B;
        if (p > i && s_lab[i] == s_lab[p]) {
            int slot = atomicAdd(&s_pcnt, 1);
            s_pbuf[slot] = (i << 16) | p;
        }
    }
    __syncthreads();
    {
        __shared__ int s_base;
        if (tid == 0 && s_pcnt > 0) s_base = atomicAdd(&g_npairs, s_pcnt);
        __syncthreads();
        if (tid < s_pcnt) g_pairlist[s_base + tid] = s_pbuf[tid];
    }

    // ---- phase A2: dist tile 32x32, double-buffered, f32x2 packed math -----
    {
        const int by = bid / 12, bx = bid % 12;
        const int i0 = by * TILE, j0 = bx * TILE;
        const int lr = tid >> 5;          // rows lr and lr+16
        const int lc = tid & 31;

        u64 acc0l = 0, acc0h = 0, acc1l = 0, acc1h = 0;   // packed f32x2 accs

        // preload + store chunk 0
        float rA0 = f[(i0 + lr)      * D + lc];
        float rA1 = f[(i0 + lr + 16) * D + lc];
        float rB0 = f[(j0 + lr)      * D + lc];
        float rB1 = f[(j0 + lr + 16) * D + lc];
        As[0][lr][lc]      = rA0;
        As[0][lr + 16][lc] = rA1;
        Bs[0][lr][lc]      = -rB0;      // negated: diff becomes packed add
        Bs[0][lr + 16][lc] = -rB1;
        __syncthreads();

#pragma unroll
        for (int c = 0; c < D / TILE; c++) {
            const int buf = c & 1;
            if (c < D / TILE - 1) {
                const int kk = (c + 1) * TILE;
                rA0 = f[(i0 + lr)      * D + kk + lc];
                rA1 = f[(i0 + lr + 16) * D + kk + lc];
                rB0 = f[(j0 + lr)      * D + kk + lc];
                rB1 = f[(j0 + lr + 16) * D + kk + lc];
            }
#pragma unroll
            for (int k4 = 0; k4 < TILE / 4; k4++) {
                ulonglong2 nb = *(const ulonglong2*)&Bs[buf][lc][k4 * 4];
                ulonglong2 a0 = *(const ulonglong2*)&As[buf][lr][k4 * 4];
                ulonglong2 a1 = *(const ulonglong2*)&As[buf][lr + 16][k4 * 4];
                u64 d0, d1, d2, d3;
                ADD2(d0, a0.x, nb.x); FMA2(acc0l, d0);
                ADD2(d1, a0.y, nb.y); FMA2(acc0h, d1);
                ADD2(d2, a1.x, nb.x); FMA2(acc1l, d2);
                ADD2(d3, a1.y, nb.y); FMA2(acc1h, d3);
            }
            if (c < D / TILE - 1) {
                const int nbuf = buf ^ 1;
                As[nbuf][lr][lc]      = rA0;    // other buffer: no hazard with
                As[nbuf][lr + 16][lc] = rA1;    // this chunk's compute
                Bs[nbuf][lr][lc]      = -rB0;
                Bs[nbuf][lr + 16][lc] = -rB1;
                __syncthreads();                // one barrier per chunk
            }
        }

        float2 p0l = *(float2*)&acc0l, p0h = *(float2*)&acc0h;
        float2 p1l = *(float2*)&acc1l, p1h = *(float2*)&acc1h;
        float s0 = (p0l.x + p0l.y) + (p0h.x + p0h.y);
        float s1 = (p1l.x + p1l.y) + (p1h.x + p1h.y);
        g_dist[(i0 + lr)      * B + j0 + lc] = sqrtf(fmaxf(s0, 1e-11f));
        g_dist[(i0 + lr + 16) * B + j0 + lc] = sqrtf(fmaxf(s1, 1e-11f));
    }

    grid_barrier();

    // ---- phase B: one warp per pair, batched loads + inlined gumbel --------
    const bool semi_mode = (epoch[0] > 3);
    const int lane  = tid & 31;
    const int gw    = bid * (NTHR / 32) + (tid >> 5);
    const int nwarp = gridDim.x * (NTHR / 32);
    const int np    = *(volatile int*)&g_npairs;

    float wsum = 0.0f;
    int   wcnt = 0;

    for (int q = gw; q < np; q += nwarp) {
        const int code = g_pairlist[q];
        const int i = code >> 16, p = code & 0xffff;
        const int li = s_lab[i];
        const float* drow = g_dist + i * B;
        const float dpos = drow[p];
        const uint32_t nbase = ((uint32_t)i * B + p) * B;

        // 1) batch all 12 candidate loads (independent -> MLP=12)
        float dv[B / 32];
#pragma unroll
        for (int s = 0; s < B / 32; s++) dv[s] = drow[s * 32 + lane];

        // 2) masks + gumbel at semi sites (inlined; chains overlap across
        //    lanes, each lane averages ~1 semi site)
        float best = -3.0e38f;
        int   bidx = 0x7fffffff;
        bool  anyf = false;
#pragma unroll
        for (int s = 0; s < B / 32; s++) {
            const int k = s * 32 + lane;
            const float dik = dv[s];
            const bool neg = (s_lab[k] != li);
            const bool semi = semi_mode
                ? (neg && dik > dpos && dik < dpos + MARGIN) : neg;
            if (semi) {
                anyf = true;
                float base = semi_mode ? -logf(dik) : 0.0f;
                float sc = base + gumbel_at(nbase + k);
                if (sc > best || (sc == best && k < bidx)) { best = sc; bidx = k; }
            }
        }
        // warp argmax, first-index tie break (matches jnp.argmax)
#pragma unroll
        for (int off = 16; off; off >>= 1) {
            float ov = __shfl_down_sync(0xffffffffu, best, off);
            int   oi = __shfl_down_sync(0xffffffffu, bidx, off);
            if (ov > best || (ov == best && oi < bidx)) { best = ov; bidx = oi; }
        }
        const bool any = __any_sync(0xffffffffu, anyf);
        if (lane == 0 && any) {
            wsum += fmaxf(dpos - drow[bidx] + MARGIN, 0.0f);
            wcnt += 1;
        }
    }

    if (lane == 0 && wcnt > 0) {
        atomicAdd(&s_total, wsum);
        atomicAdd(&s_count, wcnt);
    }
    __syncthreads();
    if (tid == 0 && s_count > 0) {
        atomicAdd(&g_total, s_total);
        atomicAdd(&g_count, s_count);
    }

    // ---- finalize: last block writes the result & resets persistent state ---
    __threadfence();
    if (tid == 0) {
        if (atomicAdd(&g_done, 1u) == gridDim.x - 1) {
            float tot = atomicAdd(&g_total, 0.0f);   // atomic read-after-fence
            int   cnt = atomicAdd(&g_count, 0);
            out[0] = (cnt > 0) ? (tot / (float)cnt) : 0.0f;
            g_total  = 0.0f;
            g_count  = 0;
            g_npairs = 0;
            __threadfence();
            atomicExch(&g_done, 0u);
        }
    }
}

// ---- launch ------------------------------------------------------------------
extern "C" void kernel_launch(void* const* d_in, const int* in_sizes, int n_in,
                              void* d_out, int out_size) {
    const float* feat   = (const float*)d_in[0];
    const int*   labels = (const int*)d_in[1];
    const int*   epoch  = (const int*)d_in[2];
    float* out = (float*)d_out;

    k_fused<<<NBLK, NTHR>>>(feat, labels, epoch, out);
}